// round 4
// baseline (speedup 1.0000x reference)
#include <cuda_runtime.h>

#define N_NODES 50000
#define N_EDGES 1600000
#define IN_DIM  128
#define HD      128          // N_HEADS * OUT_DIM
#define NHEADS  8

// Scratch (device globals: allocation-free)
__device__ float g_Q[N_NODES * HD];
__device__ float g_K[N_NODES * HD];
__device__ float g_V[N_NODES * HD];
__device__ float g_z[N_NODES * NHEADS];

// -------------------------------------------------------------------------
// Zero the output accumulator and the per-(node,head) normalizer.
// -------------------------------------------------------------------------
__global__ void zero_kernel(float* __restrict__ out) {
    int i = blockIdx.x * blockDim.x + threadIdx.x;
    if (i < N_NODES * HD) out[i] = 0.0f;
    if (i < N_NODES * NHEADS) g_z[i] = 0.0f;
}

// -------------------------------------------------------------------------
// Projection GEMM: out = state @ W + b for W in {WQ, WK, WV} (blockIdx.y).
// 128x128 output tile per block, 256 threads, 8x8 micro-tile per thread.
// Full K=128 staged in smem (state tile padded to 129 to break conflicts).
// -------------------------------------------------------------------------
__global__ void proj_kernel(const float* __restrict__ state,
                            const float* __restrict__ WQ, const float* __restrict__ bQ,
                            const float* __restrict__ WK, const float* __restrict__ bK,
                            const float* __restrict__ WV, const float* __restrict__ bV) {
    extern __shared__ float smem[];
    float* sA = smem;               // [128][129] state tile
    float* sB = smem + 128 * 129;   // [128][128] W

    const float* W; const float* bias; float* out;
    if (blockIdx.y == 0)      { W = WQ; bias = bQ; out = g_Q; }
    else if (blockIdx.y == 1) { W = WK; bias = bK; out = g_K; }
    else                      { W = WV; bias = bV; out = g_V; }

    const int tid   = threadIdx.x;       // 0..255
    const int node0 = blockIdx.x * 128;

    // Load state tile (guarded tail) -> sA[row][k], padded stride 129
    for (int t = tid; t < 128 * 32; t += 256) {       // 4096 float4 loads
        int row = t >> 5;
        int c4  = (t & 31) << 2;
        float4 v = make_float4(0.f, 0.f, 0.f, 0.f);
        int gr = node0 + row;
        if (gr < N_NODES) v = *(const float4*)&state[gr * IN_DIM + c4];
        sA[row * 129 + c4 + 0] = v.x;
        sA[row * 129 + c4 + 1] = v.y;
        sA[row * 129 + c4 + 2] = v.z;
        sA[row * 129 + c4 + 3] = v.w;
    }
    // Load W -> sB[k][j] (direct copy, row-major matches)
    for (int t = tid; t < 128 * 32; t += 256) {
        ((float4*)sB)[t] = ((const float4*)W)[t];
    }
    __syncthreads();

    const int tx = tid & 15;   // col group: cols tx*8 .. tx*8+7
    const int ty = tid >> 4;   // row group: rows ty*8 .. ty*8+7

    float acc[8][8];
#pragma unroll
    for (int i = 0; i < 8; i++)
#pragma unroll
        for (int j = 0; j < 8; j++) acc[i][j] = 0.0f;

#pragma unroll 8
    for (int k = 0; k < 128; k++) {
        float a[8];
#pragma unroll
        for (int i = 0; i < 8; i++) a[i] = sA[(ty * 8 + i) * 129 + k];
        float4 b0 = *(float4*)&sB[k * 128 + tx * 8];
        float4 b1 = *(float4*)&sB[k * 128 + tx * 8 + 4];
        float bb[8] = { b0.x, b0.y, b0.z, b0.w, b1.x, b1.y, b1.z, b1.w };
#pragma unroll
        for (int i = 0; i < 8; i++)
#pragma unroll
            for (int j = 0; j < 8; j++)
                acc[i][j] += a[i] * bb[j];
    }

    float4 bv0 = *(const float4*)&bias[tx * 8];
    float4 bv1 = *(const float4*)&bias[tx * 8 + 4];
#pragma unroll
    for (int i = 0; i < 8; i++) {
        int gr = node0 + ty * 8 + i;
        if (gr < N_NODES) {
            float4 o0 = make_float4(acc[i][0] + bv0.x, acc[i][1] + bv0.y,
                                    acc[i][2] + bv0.z, acc[i][3] + bv0.w);
            float4 o1 = make_float4(acc[i][4] + bv1.x, acc[i][5] + bv1.y,
                                    acc[i][6] + bv1.z, acc[i][7] + bv1.w);
            *(float4*)&out[gr * HD + tx * 8]     = o0;
            *(float4*)&out[gr * HD + tx * 8 + 4] = o1;
        }
    }
}

// -------------------------------------------------------------------------
// Edge kernel: one warp per edge.
//   lane l owns dims [4l, 4l+4); head h = l>>2 (4-lane groups).
//   score_h = exp(clip(sum_d K[src,h,d]*Q[dst,h,d] / 4, -5, 5))
//   out[dst] += V[src] * score  (vectorized red.global.add.v4.f32)
//   z[dst,h] += score
// -------------------------------------------------------------------------
__device__ __forceinline__ void red_add_v4(float* p, float4 v) {
    asm volatile("red.global.add.v4.f32 [%0], {%1, %2, %3, %4};"
                 :: "l"(p), "f"(v.x), "f"(v.y), "f"(v.z), "f"(v.w)
                 : "memory");
}

__global__ void edge_kernel(const int* __restrict__ src,
                            const int* __restrict__ dst,
                            float* __restrict__ out) {
    int w = (blockIdx.x * blockDim.x + threadIdx.x) >> 5;   // edge id
    if (w >= N_EDGES) return;
    const int lane = threadIdx.x & 31;

    const int s = src[w];
    const int d = dst[w];

    const float4 k4 = *(const float4*)&g_K[s * HD + lane * 4];
    const float4 q4 = *(const float4*)&g_Q[d * HD + lane * 4];
    float p = k4.x * q4.x + k4.y * q4.y + k4.z * q4.z + k4.w * q4.w;
    // reduce across the 4 lanes of each head
    p += __shfl_xor_sync(0xffffffffu, p, 1);
    p += __shfl_xor_sync(0xffffffffu, p, 2);

    float sc = __expf(fminf(fmaxf(p * 0.25f, -5.0f), 5.0f));  // 1/sqrt(16)=0.25

    const float4 v4 = *(const float4*)&g_V[s * HD + lane * 4];
    red_add_v4(&out[d * HD + lane * 4],
               make_float4(v4.x * sc, v4.y * sc, v4.z * sc, v4.w * sc));

    if ((lane & 3) == 0)
        atomicAdd(&g_z[d * NHEADS + (lane >> 2)], sc);
}

// -------------------------------------------------------------------------
// Normalize: out[n,h,d] /= z[n,h]
// -------------------------------------------------------------------------
__global__ void div_kernel(float* __restrict__ out) {
    int i = blockIdx.x * blockDim.x + threadIdx.x;
    if (i >= N_NODES * HD) return;
    int n = i >> 7;
    int h = (i >> 4) & 7;
    out[i] = out[i] / g_z[n * NHEADS + h];
}

// -------------------------------------------------------------------------
extern "C" void kernel_launch(void* const* d_in, const int* in_sizes, int n_in,
                              void* d_out, int out_size) {
    const float* state = (const float*)d_in[0];
    const int*   src   = (const int*)d_in[1];
    const int*   dst   = (const int*)d_in[2];
    const float* WQ    = (const float*)d_in[3];
    const float* bQ    = (const float*)d_in[4];
    const float* WK    = (const float*)d_in[5];
    const float* bK    = (const float*)d_in[6];
    const float* WV    = (const float*)d_in[7];
    const float* bV    = (const float*)d_in[8];
    float* out = (float*)d_out;

    // 1) zero accumulators
    zero_kernel<<<(N_NODES * HD + 255) / 256, 256>>>(out);

    // 2) Q/K/V projections
    const size_t smem_bytes = (size_t)(128 * 129 + 128 * 128) * sizeof(float);
    cudaFuncSetAttribute(proj_kernel, cudaFuncAttributeMaxDynamicSharedMemorySize,
                         (int)smem_bytes);
    dim3 pg((N_NODES + 127) / 128, 3);
    proj_kernel<<<pg, 256, smem_bytes>>>(state, WQ, bQ, WK, bK, WV, bV);

    // 3) edge scatter (1 warp per edge)
    long long nthreads = (long long)N_EDGES * 32;
    int nblocks = (int)((nthreads + 255) / 256);
    edge_kernel<<<nblocks, 256>>>(src, dst, out);

    // 4) normalize
    div_kernel<<<(N_NODES * HD + 255) / 256, 256>>>(out);
}

// round 5
// speedup vs baseline: 1.1622x; 1.1622x over previous
#include <cuda_runtime.h>

#define N_NODES 50000
#define N_EDGES 1600000
#define IN_DIM  128
#define HD      128          // N_HEADS * OUT_DIM
#define NHEADS  8

// Scratch (device globals: allocation-free)
__device__ float g_Q[N_NODES * HD];
__device__ float g_K[N_NODES * HD];
__device__ float g_V[N_NODES * HD];
__device__ int   g_cnt[N_NODES];       // in-degree histogram
__device__ int   g_off[N_NODES + 1];   // CSR offsets
__device__ int   g_cur[N_NODES];       // scatter cursors
__device__ int   g_es[N_EDGES];        // src ids, grouped by dst

// ------------------------------------------------------------------------
// f32x2 helpers (sm_103a packed fp32)
// ------------------------------------------------------------------------
__device__ __forceinline__ unsigned long long dup2(float x) {
    unsigned long long r;
    asm("mov.b64 %0, {%1, %1};" : "=l"(r) : "r"(__float_as_uint(x)));
    return r;
}
#define FMA2(d, a, b) \
    asm("fma.rn.f32x2 %0, %1, %2, %0;" : "+l"(d) : "l"(a), "l"(b))

// ------------------------------------------------------------------------
// Step 1: zero the histogram
// ------------------------------------------------------------------------
__global__ void zero_cnt_kernel() {
    int i = blockIdx.x * blockDim.x + threadIdx.x;
    if (i < N_NODES) g_cnt[i] = 0;
}

// ------------------------------------------------------------------------
// Step 2: in-degree histogram
// ------------------------------------------------------------------------
__global__ void hist_kernel(const int* __restrict__ dst) {
    int e = blockIdx.x * blockDim.x + threadIdx.x;
    if (e < N_EDGES) atomicAdd(&g_cnt[dst[e]], 1);
}

// ------------------------------------------------------------------------
// Step 3: exclusive scan over g_cnt -> g_off, g_cur (single block)
// ------------------------------------------------------------------------
__global__ void scan_kernel() {
    __shared__ int sums[1024];
    const int tid = threadIdx.x;
    const int CH  = (N_NODES + 1023) / 1024;   // 49
    const int base = tid * CH;

    int s = 0;
    for (int i = 0; i < CH; i++) {
        int idx = base + i;
        if (idx < N_NODES) s += g_cnt[idx];
    }
    sums[tid] = s;
    __syncthreads();

    // inclusive Hillis-Steele scan over the 1024 partials
    for (int off = 1; off < 1024; off <<= 1) {
        int t = (tid >= off) ? sums[tid - off] : 0;
        __syncthreads();
        sums[tid] += t;
        __syncthreads();
    }

    int run = sums[tid] - s;   // exclusive prefix of this chunk
    for (int i = 0; i < CH; i++) {
        int idx = base + i;
        if (idx < N_NODES) {
            g_off[idx] = run;
            g_cur[idx] = run;
            run += g_cnt[idx];
        }
    }
    if (tid == 1023) g_off[N_NODES] = N_EDGES;
}

// ------------------------------------------------------------------------
// Step 4: scatter edges into dst-grouped order
// ------------------------------------------------------------------------
__global__ void scatter_kernel(const int* __restrict__ src,
                               const int* __restrict__ dst) {
    int e = blockIdx.x * blockDim.x + threadIdx.x;
    if (e >= N_EDGES) return;
    int pos = atomicAdd(&g_cur[dst[e]], 1);
    g_es[pos] = src[e];
}

// ------------------------------------------------------------------------
// Projection GEMM with packed f32x2 FMA:
//   out = state @ W + b for W in {WQ, WK, WV} (blockIdx.y).
// 128x128 tile / block, 256 threads, 8x8 micro-tile (j packed in pairs).
// ------------------------------------------------------------------------
__global__ void __launch_bounds__(256, 1)
proj_kernel(const float* __restrict__ state,
            const float* __restrict__ WQ, const float* __restrict__ bQ,
            const float* __restrict__ WK, const float* __restrict__ bK,
            const float* __restrict__ WV, const float* __restrict__ bV) {
    extern __shared__ float smem[];
    float* sA = smem;               // [128][129] state tile (padded)
    float* sB = smem + 128 * 129;   // [128][128] W

    const float* W; const float* bias; float* out;
    if (blockIdx.y == 0)      { W = WQ; bias = bQ; out = g_Q; }
    else if (blockIdx.y == 1) { W = WK; bias = bK; out = g_K; }
    else                      { W = WV; bias = bV; out = g_V; }

    const int tid   = threadIdx.x;       // 0..255
    const int node0 = blockIdx.x * 128;

    for (int t = tid; t < 128 * 32; t += 256) {      // state tile
        int row = t >> 5;
        int c4  = (t & 31) << 2;
        float4 v = make_float4(0.f, 0.f, 0.f, 0.f);
        int gr = node0 + row;
        if (gr < N_NODES) v = *(const float4*)&state[gr * IN_DIM + c4];
        sA[row * 129 + c4 + 0] = v.x;
        sA[row * 129 + c4 + 1] = v.y;
        sA[row * 129 + c4 + 2] = v.z;
        sA[row * 129 + c4 + 3] = v.w;
    }
    for (int t = tid; t < 128 * 32; t += 256) {      // W
        ((float4*)sB)[t] = ((const float4*)W)[t];
    }
    __syncthreads();

    const int tx = tid & 15;   // cols tx*8 .. tx*8+7
    const int ty = tid >> 4;   // rows ty*8 .. ty*8+7

    unsigned long long acc2[8][4];
#pragma unroll
    for (int i = 0; i < 8; i++)
#pragma unroll
        for (int jj = 0; jj < 4; jj++) acc2[i][jj] = 0ull;

#pragma unroll 4
    for (int k = 0; k < 128; k++) {
        unsigned long long av[8];
#pragma unroll
        for (int i = 0; i < 8; i++)
            av[i] = dup2(sA[(ty * 8 + i) * 129 + k]);
        unsigned long long bv[4];
#pragma unroll
        for (int jj = 0; jj < 4; jj++)
            bv[jj] = *(const unsigned long long*)&sB[k * 128 + tx * 8 + jj * 2];
#pragma unroll
        for (int i = 0; i < 8; i++)
#pragma unroll
            for (int jj = 0; jj < 4; jj++)
                FMA2(acc2[i][jj], av[i], bv[jj]);
    }

    float bb[8];
    {
        float4 b0 = *(const float4*)&bias[tx * 8];
        float4 b1 = *(const float4*)&bias[tx * 8 + 4];
        bb[0] = b0.x; bb[1] = b0.y; bb[2] = b0.z; bb[3] = b0.w;
        bb[4] = b1.x; bb[5] = b1.y; bb[6] = b1.z; bb[7] = b1.w;
    }
#pragma unroll
    for (int i = 0; i < 8; i++) {
        int gr = node0 + ty * 8 + i;
        if (gr < N_NODES) {
            float o[8];
#pragma unroll
            for (int jj = 0; jj < 4; jj++) {
                o[jj * 2 + 0] = __uint_as_float((unsigned)(acc2[i][jj])) + bb[jj * 2];
                o[jj * 2 + 1] = __uint_as_float((unsigned)(acc2[i][jj] >> 32)) + bb[jj * 2 + 1];
            }
            *(float4*)&out[gr * HD + tx * 8]     = make_float4(o[0], o[1], o[2], o[3]);
            *(float4*)&out[gr * HD + tx * 8 + 4] = make_float4(o[4], o[5], o[6], o[7]);
        }
    }
}

// ------------------------------------------------------------------------
// Aggregation: one warp per destination node (gather, no atomics).
//   lane l owns dims [4l, 4l+4); head h = l>>2.
//   Q[dst] register-resident; loop over grouped in-edges; normalized write.
// ------------------------------------------------------------------------
__global__ void agg_kernel(float* __restrict__ out) {
    int node = (blockIdx.x * blockDim.x + threadIdx.x) >> 5;
    if (node >= N_NODES) return;
    const int lane = threadIdx.x & 31;

    const float4 q4 = *(const float4*)&g_Q[node * HD + lane * 4];
    float4 acc = make_float4(0.f, 0.f, 0.f, 0.f);
    float accZ = 0.f;

    int j   = g_off[node];
    int end = g_off[node + 1];

    // 2x unrolled for load-level parallelism
    for (; j + 1 < end; j += 2) {
        int s0 = g_es[j];
        int s1 = g_es[j + 1];
        float4 k0 = *(const float4*)&g_K[s0 * HD + lane * 4];
        float4 k1 = *(const float4*)&g_K[s1 * HD + lane * 4];
        float4 v0 = *(const float4*)&g_V[s0 * HD + lane * 4];
        float4 v1 = *(const float4*)&g_V[s1 * HD + lane * 4];

        float p0 = k0.x * q4.x + k0.y * q4.y + k0.z * q4.z + k0.w * q4.w;
        float p1 = k1.x * q4.x + k1.y * q4.y + k1.z * q4.z + k1.w * q4.w;
        p0 += __shfl_xor_sync(0xffffffffu, p0, 1);
        p1 += __shfl_xor_sync(0xffffffffu, p1, 1);
        p0 += __shfl_xor_sync(0xffffffffu, p0, 2);
        p1 += __shfl_xor_sync(0xffffffffu, p1, 2);

        float sc0 = __expf(fminf(fmaxf(p0 * 0.25f, -5.0f), 5.0f));
        float sc1 = __expf(fminf(fmaxf(p1 * 0.25f, -5.0f), 5.0f));

        acc.x += v0.x * sc0 + v1.x * sc1;
        acc.y += v0.y * sc0 + v1.y * sc1;
        acc.z += v0.z * sc0 + v1.z * sc1;
        acc.w += v0.w * sc0 + v1.w * sc1;
        accZ  += sc0 + sc1;
    }
    if (j < end) {
        int s0 = g_es[j];
        float4 k0 = *(const float4*)&g_K[s0 * HD + lane * 4];
        float4 v0 = *(const float4*)&g_V[s0 * HD + lane * 4];
        float p0 = k0.x * q4.x + k0.y * q4.y + k0.z * q4.z + k0.w * q4.w;
        p0 += __shfl_xor_sync(0xffffffffu, p0, 1);
        p0 += __shfl_xor_sync(0xffffffffu, p0, 2);
        float sc0 = __expf(fminf(fmaxf(p0 * 0.25f, -5.0f), 5.0f));
        acc.x += v0.x * sc0; acc.y += v0.y * sc0;
        acc.z += v0.z * sc0; acc.w += v0.w * sc0;
        accZ  += sc0;
    }

    *(float4*)&out[node * HD + lane * 4] =
        make_float4(acc.x / accZ, acc.y / accZ, acc.z / accZ, acc.w / accZ);
}

// ------------------------------------------------------------------------
extern "C" void kernel_launch(void* const* d_in, const int* in_sizes, int n_in,
                              void* d_out, int out_size) {
    const float* state = (const float*)d_in[0];
    const int*   src   = (const int*)d_in[1];
    const int*   dst   = (const int*)d_in[2];
    const float* WQ    = (const float*)d_in[3];
    const float* bQ    = (const float*)d_in[4];
    const float* WK    = (const float*)d_in[5];
    const float* bK    = (const float*)d_in[6];
    const float* WV    = (const float*)d_in[7];
    const float* bV    = (const float*)d_in[8];
    float* out = (float*)d_out;

    // CSR build: zero -> histogram -> scan -> scatter
    zero_cnt_kernel<<<(N_NODES + 255) / 256, 256>>>();
    hist_kernel<<<(N_EDGES + 255) / 256, 256>>>(dst);
    scan_kernel<<<1, 1024>>>();
    scatter_kernel<<<(N_EDGES + 255) / 256, 256>>>(src, dst);

    // Q/K/V projections (f32x2-packed GEMM)
    const size_t smem_bytes = (size_t)(128 * 129 + 128 * 128) * sizeof(float);
    cudaFuncSetAttribute(proj_kernel, cudaFuncAttributeMaxDynamicSharedMemorySize,
                         (int)smem_bytes);
    dim3 pg((N_NODES + 127) / 128, 3);
    proj_kernel<<<pg, 256, smem_bytes>>>(state, WQ, bQ, WK, bK, WV, bV);

    // gather-aggregate + fused normalize (1 warp per node)
    long long nthreads = (long long)N_NODES * 32;
    int nblocks = (int)((nthreads + 255) / 256);
    agg_kernel<<<nblocks, 256>>>(out);
}

// round 6
// speedup vs baseline: 1.2284x; 1.0569x over previous
#include <cuda_runtime.h>

#define N_NODES 50000
#define N_EDGES 1600000
#define IN_DIM  128
#define HD      128          // N_HEADS * OUT_DIM
#define NHEADS  8

// Scratch (device globals: allocation-free)
__device__ float g_Q[N_NODES * HD];
__device__ float g_K[N_NODES * HD];
__device__ float g_V[N_NODES * HD];
__device__ int   g_cnt[N_NODES];       // in-degree histogram
__device__ int   g_off[N_NODES + 1];   // CSR offsets
__device__ int   g_cur[N_NODES];       // scatter cursors
__device__ int   g_es[N_EDGES];        // src ids, grouped by dst

// ------------------------------------------------------------------------
// f32x2 helpers (sm_103a packed fp32)
// ------------------------------------------------------------------------
__device__ __forceinline__ unsigned long long dup2(float x) {
    unsigned long long r;
    asm("mov.b64 %0, {%1, %1};" : "=l"(r) : "r"(__float_as_uint(x)));
    return r;
}
#define FMA2(d, a, b) \
    asm("fma.rn.f32x2 %0, %1, %2, %0;" : "+l"(d) : "l"(a), "l"(b))

// ------------------------------------------------------------------------
// Step 1: zero the histogram
// ------------------------------------------------------------------------
__global__ void zero_cnt_kernel() {
    int i = blockIdx.x * blockDim.x + threadIdx.x;
    if (i < N_NODES) g_cnt[i] = 0;
}

// ------------------------------------------------------------------------
// Step 2: in-degree histogram, 4 edges per thread (independent REDs)
// ------------------------------------------------------------------------
__global__ void hist_kernel(const int* __restrict__ dst) {
    int t = blockIdx.x * blockDim.x + threadIdx.x;
    int e0 = t * 4;
    if (e0 + 3 < N_EDGES) {
        int4 d4 = *(const int4*)&dst[e0];
        atomicAdd(&g_cnt[d4.x], 1);
        atomicAdd(&g_cnt[d4.y], 1);
        atomicAdd(&g_cnt[d4.z], 1);
        atomicAdd(&g_cnt[d4.w], 1);
    } else {
        for (int e = e0; e < N_EDGES; e++) atomicAdd(&g_cnt[dst[e]], 1);
    }
}

// ------------------------------------------------------------------------
// Step 3: exclusive scan over g_cnt -> g_off, g_cur (single block)
// ------------------------------------------------------------------------
__global__ void scan_kernel() {
    __shared__ int sums[1024];
    const int tid = threadIdx.x;
    const int CH  = (N_NODES + 1023) / 1024;   // 49
    const int base = tid * CH;

    int s = 0;
    for (int i = 0; i < CH; i++) {
        int idx = base + i;
        if (idx < N_NODES) s += g_cnt[idx];
    }
    sums[tid] = s;
    __syncthreads();

    for (int off = 1; off < 1024; off <<= 1) {
        int t = (tid >= off) ? sums[tid - off] : 0;
        __syncthreads();
        sums[tid] += t;
        __syncthreads();
    }

    int run = sums[tid] - s;   // exclusive prefix of this chunk
    for (int i = 0; i < CH; i++) {
        int idx = base + i;
        if (idx < N_NODES) {
            g_off[idx] = run;
            g_cur[idx] = run;
            run += g_cnt[idx];
        }
    }
    if (tid == 1023) g_off[N_NODES] = N_EDGES;
}

// ------------------------------------------------------------------------
// Step 4: scatter edges into dst-grouped order, 4 edges per thread
// ------------------------------------------------------------------------
__global__ void scatter_kernel(const int* __restrict__ src,
                               const int* __restrict__ dst) {
    int t = blockIdx.x * blockDim.x + threadIdx.x;
    int e0 = t * 4;
    if (e0 + 3 < N_EDGES) {
        int4 d4 = *(const int4*)&dst[e0];
        int4 s4 = *(const int4*)&src[e0];
        int p0 = atomicAdd(&g_cur[d4.x], 1);
        int p1 = atomicAdd(&g_cur[d4.y], 1);
        int p2 = atomicAdd(&g_cur[d4.z], 1);
        int p3 = atomicAdd(&g_cur[d4.w], 1);
        g_es[p0] = s4.x;
        g_es[p1] = s4.y;
        g_es[p2] = s4.z;
        g_es[p3] = s4.w;
    } else {
        for (int e = e0; e < N_EDGES; e++) {
            int pos = atomicAdd(&g_cur[dst[e]], 1);
            g_es[pos] = src[e];
        }
    }
}

// ------------------------------------------------------------------------
// Projection GEMM with packed f32x2 FMA:
//   out = state @ W + b for W in {WQ, WK, WV} (blockIdx.y).
// 128x128 tile / block, 256 threads, 8x8 micro-tile (j packed in pairs).
// ------------------------------------------------------------------------
__global__ void __launch_bounds__(256, 1)
proj_kernel(const float* __restrict__ state,
            const float* __restrict__ WQ, const float* __restrict__ bQ,
            const float* __restrict__ WK, const float* __restrict__ bK,
            const float* __restrict__ WV, const float* __restrict__ bV) {
    extern __shared__ float smem[];
    float* sA = smem;               // [128][129] state tile (padded)
    float* sB = smem + 128 * 129;   // [128][128] W

    const float* W; const float* bias; float* out;
    if (blockIdx.y == 0)      { W = WQ; bias = bQ; out = g_Q; }
    else if (blockIdx.y == 1) { W = WK; bias = bK; out = g_K; }
    else                      { W = WV; bias = bV; out = g_V; }

    const int tid   = threadIdx.x;       // 0..255
    const int node0 = blockIdx.x * 128;

    for (int t = tid; t < 128 * 32; t += 256) {      // state tile
        int row = t >> 5;
        int c4  = (t & 31) << 2;
        float4 v = make_float4(0.f, 0.f, 0.f, 0.f);
        int gr = node0 + row;
        if (gr < N_NODES) v = *(const float4*)&state[gr * IN_DIM + c4];
        sA[row * 129 + c4 + 0] = v.x;
        sA[row * 129 + c4 + 1] = v.y;
        sA[row * 129 + c4 + 2] = v.z;
        sA[row * 129 + c4 + 3] = v.w;
    }
    for (int t = tid; t < 128 * 32; t += 256) {      // W
        ((float4*)sB)[t] = ((const float4*)W)[t];
    }
    __syncthreads();

    const int tx = tid & 15;   // cols tx*8 .. tx*8+7
    const int ty = tid >> 4;   // rows ty*8 .. ty*8+7

    unsigned long long acc2[8][4];
#pragma unroll
    for (int i = 0; i < 8; i++)
#pragma unroll
        for (int jj = 0; jj < 4; jj++) acc2[i][jj] = 0ull;

#pragma unroll 4
    for (int k = 0; k < 128; k++) {
        unsigned long long av[8];
#pragma unroll
        for (int i = 0; i < 8; i++)
            av[i] = dup2(sA[(ty * 8 + i) * 129 + k]);
        unsigned long long bv[4];
#pragma unroll
        for (int jj = 0; jj < 4; jj++)
            bv[jj] = *(const unsigned long long*)&sB[k * 128 + tx * 8 + jj * 2];
#pragma unroll
        for (int i = 0; i < 8; i++)
#pragma unroll
            for (int jj = 0; jj < 4; jj++)
                FMA2(acc2[i][jj], av[i], bv[jj]);
    }

    float bb[8];
    {
        float4 b0 = *(const float4*)&bias[tx * 8];
        float4 b1 = *(const float4*)&bias[tx * 8 + 4];
        bb[0] = b0.x; bb[1] = b0.y; bb[2] = b0.z; bb[3] = b0.w;
        bb[4] = b1.x; bb[5] = b1.y; bb[6] = b1.z; bb[7] = b1.w;
    }
#pragma unroll
    for (int i = 0; i < 8; i++) {
        int gr = node0 + ty * 8 + i;
        if (gr < N_NODES) {
            float o[8];
#pragma unroll
            for (int jj = 0; jj < 4; jj++) {
                o[jj * 2 + 0] = __uint_as_float((unsigned)(acc2[i][jj])) + bb[jj * 2];
                o[jj * 2 + 1] = __uint_as_float((unsigned)(acc2[i][jj] >> 32)) + bb[jj * 2 + 1];
            }
            *(float4*)&out[gr * HD + tx * 8]     = make_float4(o[0], o[1], o[2], o[3]);
            *(float4*)&out[gr * HD + tx * 8 + 4] = make_float4(o[4], o[5], o[6], o[7]);
        }
    }
}

// ------------------------------------------------------------------------
// Aggregation: one warp per destination node (gather, no atomics).
//   lane l owns dims [4l, 4l+4); head h = l>>2.
//   Q[dst] register-resident; 4x-unrolled edge loop (8 LDG.128 in flight);
//   fused normalize on the single output write.
// ------------------------------------------------------------------------
__device__ __forceinline__ float edge_score(float4 k, float4 q) {
    float p = k.x * q.x + k.y * q.y + k.z * q.z + k.w * q.w;
    p += __shfl_xor_sync(0xffffffffu, p, 1);
    p += __shfl_xor_sync(0xffffffffu, p, 2);
    return __expf(fminf(fmaxf(p * 0.25f, -5.0f), 5.0f));
}

__global__ void agg_kernel(float* __restrict__ out) {
    int node = (blockIdx.x * blockDim.x + threadIdx.x) >> 5;
    if (node >= N_NODES) return;
    const int lane = threadIdx.x & 31;
    const int off4 = lane * 4;

    const float4 q4 = *(const float4*)&g_Q[node * HD + off4];
    float4 acc = make_float4(0.f, 0.f, 0.f, 0.f);
    float accZ = 0.f;

    int j   = g_off[node];
    int end = g_off[node + 1];

    for (; j + 3 < end; j += 4) {
        int s0 = g_es[j];
        int s1 = g_es[j + 1];
        int s2 = g_es[j + 2];
        int s3 = g_es[j + 3];
        float4 k0 = *(const float4*)&g_K[s0 * HD + off4];
        float4 k1 = *(const float4*)&g_K[s1 * HD + off4];
        float4 k2 = *(const float4*)&g_K[s2 * HD + off4];
        float4 k3 = *(const float4*)&g_K[s3 * HD + off4];
        float4 v0 = *(const float4*)&g_V[s0 * HD + off4];
        float4 v1 = *(const float4*)&g_V[s1 * HD + off4];
        float4 v2 = *(const float4*)&g_V[s2 * HD + off4];
        float4 v3 = *(const float4*)&g_V[s3 * HD + off4];

        float sc0 = edge_score(k0, q4);
        float sc1 = edge_score(k1, q4);
        float sc2 = edge_score(k2, q4);
        float sc3 = edge_score(k3, q4);

        acc.x += v0.x * sc0 + v1.x * sc1 + v2.x * sc2 + v3.x * sc3;
        acc.y += v0.y * sc0 + v1.y * sc1 + v2.y * sc2 + v3.y * sc3;
        acc.z += v0.z * sc0 + v1.z * sc1 + v2.z * sc2 + v3.z * sc3;
        acc.w += v0.w * sc0 + v1.w * sc1 + v2.w * sc2 + v3.w * sc3;
        accZ  += sc0 + sc1 + sc2 + sc3;
    }
    for (; j < end; j++) {
        int s0 = g_es[j];
        float4 k0 = *(const float4*)&g_K[s0 * HD + off4];
        float4 v0 = *(const float4*)&g_V[s0 * HD + off4];
        float sc0 = edge_score(k0, q4);
        acc.x += v0.x * sc0; acc.y += v0.y * sc0;
        acc.z += v0.z * sc0; acc.w += v0.w * sc0;
        accZ  += sc0;
    }

    *(float4*)&out[node * HD + off4] =
        make_float4(acc.x / accZ, acc.y / accZ, acc.z / accZ, acc.w / accZ);
}

// ------------------------------------------------------------------------
extern "C" void kernel_launch(void* const* d_in, const int* in_sizes, int n_in,
                              void* d_out, int out_size) {
    const float* state = (const float*)d_in[0];
    const int*   src   = (const int*)d_in[1];
    const int*   dst   = (const int*)d_in[2];
    const float* WQ    = (const float*)d_in[3];
    const float* bQ    = (const float*)d_in[4];
    const float* WK    = (const float*)d_in[5];
    const float* bK    = (const float*)d_in[6];
    const float* WV    = (const float*)d_in[7];
    const float* bV    = (const float*)d_in[8];
    float* out = (float*)d_out;

    // Side stream + events for CSR-build || proj-GEMM overlap.
    // Created once on the first (non-captured correctness) call.
    static cudaStream_t s_csr = nullptr;
    static cudaEvent_t  ev_fork = nullptr, ev_join = nullptr;
    if (s_csr == nullptr) {
        cudaStreamCreateWithFlags(&s_csr, cudaStreamNonBlocking);
        cudaEventCreateWithFlags(&ev_fork, cudaEventDisableTiming);
        cudaEventCreateWithFlags(&ev_join, cudaEventDisableTiming);
    }

    // Fork: CSR build on side stream
    cudaEventRecord(ev_fork, 0);
    cudaStreamWaitEvent(s_csr, ev_fork, 0);

    zero_cnt_kernel<<<(N_NODES + 255) / 256, 256, 0, s_csr>>>();
    {
        int nthr = (N_EDGES + 3) / 4;
        hist_kernel<<<(nthr + 255) / 256, 256, 0, s_csr>>>(dst);
    }
    scan_kernel<<<1, 1024, 0, s_csr>>>();
    {
        int nthr = (N_EDGES + 3) / 4;
        scatter_kernel<<<(nthr + 255) / 256, 256, 0, s_csr>>>(src, dst);
    }
    cudaEventRecord(ev_join, s_csr);

    // Meanwhile: Q/K/V projections (f32x2-packed GEMM) on main stream
    const size_t smem_bytes = (size_t)(128 * 129 + 128 * 128) * sizeof(float);
    cudaFuncSetAttribute(proj_kernel, cudaFuncAttributeMaxDynamicSharedMemorySize,
                         (int)smem_bytes);
    dim3 pg((N_NODES + 127) / 128, 3);
    proj_kernel<<<pg, 256, smem_bytes>>>(state, WQ, bQ, WK, bK, WV, bV);

    // Join: agg needs both CSR and projections
    cudaStreamWaitEvent(0, ev_join, 0);

    long long nthreads = (long long)N_NODES * 32;
    int nblocks = (int)((nthreads + 255) / 256);
    agg_kernel<<<nblocks, 256>>>(out);
}

// round 7
// speedup vs baseline: 1.3110x; 1.0673x over previous
#include <cuda_runtime.h>
#include <cuda_fp16.h>

#define N_NODES 50000
#define N_EDGES 1600000
#define IN_DIM  128
#define HD      128          // N_HEADS * OUT_DIM
#define NHEADS  8

// Scratch (device globals: allocation-free)
__device__ float  g_Q[N_NODES * HD];
// Interleaved fp16 K/V: per node, 32 lane-slots of 8 halves = {k0..k3, v0..v3}.
// Lane l's 16-byte slot covers dims [4l,4l+4) of both K and V.
__device__ __half g_KV[N_NODES * 256];
__device__ int    g_cnt[N_NODES];       // in-degree histogram
__device__ int    g_off[N_NODES + 1];   // CSR offsets
__device__ int    g_cur[N_NODES];       // scatter cursors
__device__ int    g_es[N_EDGES];        // src ids, grouped by dst

// ------------------------------------------------------------------------
// f32x2 helpers (sm_103a packed fp32)
// ------------------------------------------------------------------------
__device__ __forceinline__ unsigned long long dup2(float x) {
    unsigned long long r;
    asm("mov.b64 %0, {%1, %1};" : "=l"(r) : "r"(__float_as_uint(x)));
    return r;
}
#define FMA2(d, a, b) \
    asm("fma.rn.f32x2 %0, %1, %2, %0;" : "+l"(d) : "l"(a), "l"(b))

// ------------------------------------------------------------------------
// CSR build
// ------------------------------------------------------------------------
__global__ void zero_cnt_kernel() {
    int i = blockIdx.x * blockDim.x + threadIdx.x;
    if (i < N_NODES) g_cnt[i] = 0;
}

__global__ void hist_kernel(const int* __restrict__ dst) {
    int t = blockIdx.x * blockDim.x + threadIdx.x;
    int e0 = t * 4;
    if (e0 + 3 < N_EDGES) {
        int4 d4 = *(const int4*)&dst[e0];
        atomicAdd(&g_cnt[d4.x], 1);
        atomicAdd(&g_cnt[d4.y], 1);
        atomicAdd(&g_cnt[d4.z], 1);
        atomicAdd(&g_cnt[d4.w], 1);
    } else {
        for (int e = e0; e < N_EDGES; e++) atomicAdd(&g_cnt[dst[e]], 1);
    }
}

__global__ void scan_kernel() {
    __shared__ int sums[1024];
    const int tid = threadIdx.x;
    const int CH  = (N_NODES + 1023) / 1024;   // 49
    const int base = tid * CH;

    int s = 0;
    for (int i = 0; i < CH; i++) {
        int idx = base + i;
        if (idx < N_NODES) s += g_cnt[idx];
    }
    sums[tid] = s;
    __syncthreads();

    for (int off = 1; off < 1024; off <<= 1) {
        int t = (tid >= off) ? sums[tid - off] : 0;
        __syncthreads();
        sums[tid] += t;
        __syncthreads();
    }

    int run = sums[tid] - s;   // exclusive prefix of this chunk
    for (int i = 0; i < CH; i++) {
        int idx = base + i;
        if (idx < N_NODES) {
            g_off[idx] = run;
            g_cur[idx] = run;
            run += g_cnt[idx];
        }
    }
    if (tid == 1023) g_off[N_NODES] = N_EDGES;
}

__global__ void scatter_kernel(const int* __restrict__ src,
                               const int* __restrict__ dst) {
    int t = blockIdx.x * blockDim.x + threadIdx.x;
    int e0 = t * 4;
    if (e0 + 3 < N_EDGES) {
        int4 d4 = *(const int4*)&dst[e0];
        int4 s4 = *(const int4*)&src[e0];
        int p0 = atomicAdd(&g_cur[d4.x], 1);
        int p1 = atomicAdd(&g_cur[d4.y], 1);
        int p2 = atomicAdd(&g_cur[d4.z], 1);
        int p3 = atomicAdd(&g_cur[d4.w], 1);
        g_es[p0] = s4.x;
        g_es[p1] = s4.y;
        g_es[p2] = s4.z;
        g_es[p3] = s4.w;
    } else {
        for (int e = e0; e < N_EDGES; e++) {
            int pos = atomicAdd(&g_cur[dst[e]], 1);
            g_es[pos] = src[e];
        }
    }
}

// ------------------------------------------------------------------------
// Projection GEMM with packed f32x2 FMA:
//   blockIdx.y: 0 -> Q (fp32 to g_Q)
//               1 -> K (fp16, interleaved into g_KV at slot offset 0)
//               2 -> V (fp16, interleaved into g_KV at slot offset 4)
// 128x128 tile / block, 256 threads, 8x8 micro-tile (j packed in pairs).
// ------------------------------------------------------------------------
__global__ void __launch_bounds__(256, 1)
proj_kernel(const float* __restrict__ state,
            const float* __restrict__ WQ, const float* __restrict__ bQ,
            const float* __restrict__ WK, const float* __restrict__ bK,
            const float* __restrict__ WV, const float* __restrict__ bV) {
    extern __shared__ float smem[];
    float* sA = smem;               // [128][129] state tile (padded)
    float* sB = smem + 128 * 129;   // [128][128] W

    const float* W; const float* bias;
    if (blockIdx.y == 0)      { W = WQ; bias = bQ; }
    else if (blockIdx.y == 1) { W = WK; bias = bK; }
    else                      { W = WV; bias = bV; }

    const int tid   = threadIdx.x;       // 0..255
    const int node0 = blockIdx.x * 128;

    for (int t = tid; t < 128 * 32; t += 256) {      // state tile
        int row = t >> 5;
        int c4  = (t & 31) << 2;
        float4 v = make_float4(0.f, 0.f, 0.f, 0.f);
        int gr = node0 + row;
        if (gr < N_NODES) v = *(const float4*)&state[gr * IN_DIM + c4];
        sA[row * 129 + c4 + 0] = v.x;
        sA[row * 129 + c4 + 1] = v.y;
        sA[row * 129 + c4 + 2] = v.z;
        sA[row * 129 + c4 + 3] = v.w;
    }
    for (int t = tid; t < 128 * 32; t += 256) {      // W
        ((float4*)sB)[t] = ((const float4*)W)[t];
    }
    __syncthreads();

    const int tx = tid & 15;   // cols tx*8 .. tx*8+7
    const int ty = tid >> 4;   // rows ty*8 .. ty*8+7

    unsigned long long acc2[8][4];
#pragma unroll
    for (int i = 0; i < 8; i++)
#pragma unroll
        for (int jj = 0; jj < 4; jj++) acc2[i][jj] = 0ull;

#pragma unroll 4
    for (int k = 0; k < 128; k++) {
        unsigned long long av[8];
#pragma unroll
        for (int i = 0; i < 8; i++)
            av[i] = dup2(sA[(ty * 8 + i) * 129 + k]);
        unsigned long long bv[4];
#pragma unroll
        for (int jj = 0; jj < 4; jj++)
            bv[jj] = *(const unsigned long long*)&sB[k * 128 + tx * 8 + jj * 2];
#pragma unroll
        for (int i = 0; i < 8; i++)
#pragma unroll
            for (int jj = 0; jj < 4; jj++)
                FMA2(acc2[i][jj], av[i], bv[jj]);
    }

    float bb[8];
    {
        float4 b0 = *(const float4*)&bias[tx * 8];
        float4 b1 = *(const float4*)&bias[tx * 8 + 4];
        bb[0] = b0.x; bb[1] = b0.y; bb[2] = b0.z; bb[3] = b0.w;
        bb[4] = b1.x; bb[5] = b1.y; bb[6] = b1.z; bb[7] = b1.w;
    }

    const int kvoff = (blockIdx.y == 1) ? 0 : 4;   // K -> slot[0:4], V -> slot[4:8]
#pragma unroll
    for (int i = 0; i < 8; i++) {
        int gr = node0 + ty * 8 + i;
        if (gr < N_NODES) {
            float o[8];
#pragma unroll
            for (int jj = 0; jj < 4; jj++) {
                o[jj * 2 + 0] = __uint_as_float((unsigned)(acc2[i][jj])) + bb[jj * 2];
                o[jj * 2 + 1] = __uint_as_float((unsigned)(acc2[i][jj] >> 32)) + bb[jj * 2 + 1];
            }
            if (blockIdx.y == 0) {
                *(float4*)&g_Q[gr * HD + tx * 8]     = make_float4(o[0], o[1], o[2], o[3]);
                *(float4*)&g_Q[gr * HD + tx * 8 + 4] = make_float4(o[4], o[5], o[6], o[7]);
            } else {
                // cols tx*8..tx*8+7 cover lanes 2*tx (dims 0..3) and 2*tx+1 (dims 4..7)
                __half2 h0 = __floats2half2_rn(o[0], o[1]);
                __half2 h1 = __floats2half2_rn(o[2], o[3]);
                __half2 h2 = __floats2half2_rn(o[4], o[5]);
                __half2 h3 = __floats2half2_rn(o[6], o[7]);
                uint2 p0, p1;
                p0.x = *(unsigned*)&h0; p0.y = *(unsigned*)&h1;
                p1.x = *(unsigned*)&h2; p1.y = *(unsigned*)&h3;
                *(uint2*)&g_KV[gr * 256 + (2 * tx)     * 8 + kvoff] = p0;
                *(uint2*)&g_KV[gr * 256 + (2 * tx + 1) * 8 + kvoff] = p1;
            }
        }
    }
}

// ------------------------------------------------------------------------
// Aggregation: one warp per destination node (gather, no atomics).
//   lane l owns dims [4l,4l+4); head h = l>>2.
//   Q[dst] register-resident (fp32); per edge per lane ONE LDG.128 pulls
//   the interleaved fp16 {K,V} slot. Fused normalize on the single write.
// ------------------------------------------------------------------------
__device__ __forceinline__ float edge_score4(float2 k0, float2 k1, float4 q) {
    float p = k0.x * q.x + k0.y * q.y + k1.x * q.z + k1.y * q.w;
    p += __shfl_xor_sync(0xffffffffu, p, 1);
    p += __shfl_xor_sync(0xffffffffu, p, 2);
    return __expf(fminf(fmaxf(p * 0.25f, -5.0f), 5.0f));
}

__device__ __forceinline__ void kv_unpack(uint4 kv, float2& k0, float2& k1,
                                          float2& v0, float2& v1) {
    k0 = __half22float2(*(__half2*)&kv.x);
    k1 = __half22float2(*(__half2*)&kv.y);
    v0 = __half22float2(*(__half2*)&kv.z);
    v1 = __half22float2(*(__half2*)&kv.w);
}

__global__ void agg_kernel(float* __restrict__ out) {
    int node = (blockIdx.x * blockDim.x + threadIdx.x) >> 5;
    if (node >= N_NODES) return;
    const int lane  = threadIdx.x & 31;
    const int slot  = lane * 8;          // half offset of this lane's KV slot

    const float4 q4 = *(const float4*)&g_Q[node * HD + lane * 4];
    float4 acc = make_float4(0.f, 0.f, 0.f, 0.f);
    float accZ = 0.f;

    int j   = g_off[node];
    int end = g_off[node + 1];

    for (; j + 3 < end; j += 4) {
        int s0 = g_es[j];
        int s1 = g_es[j + 1];
        int s2 = g_es[j + 2];
        int s3 = g_es[j + 3];
        uint4 kv0 = *(const uint4*)&g_KV[s0 * 256 + slot];
        uint4 kv1 = *(const uint4*)&g_KV[s1 * 256 + slot];
        uint4 kv2 = *(const uint4*)&g_KV[s2 * 256 + slot];
        uint4 kv3 = *(const uint4*)&g_KV[s3 * 256 + slot];

        float2 ka0, ka1, va0, va1; kv_unpack(kv0, ka0, ka1, va0, va1);
        float2 kb0, kb1, vb0, vb1; kv_unpack(kv1, kb0, kb1, vb0, vb1);
        float2 kc0, kc1, vc0, vc1; kv_unpack(kv2, kc0, kc1, vc0, vc1);
        float2 kd0, kd1, vd0, vd1; kv_unpack(kv3, kd0, kd1, vd0, vd1);

        float sc0 = edge_score4(ka0, ka1, q4);
        float sc1 = edge_score4(kb0, kb1, q4);
        float sc2 = edge_score4(kc0, kc1, q4);
        float sc3 = edge_score4(kd0, kd1, q4);

        acc.x += va0.x * sc0 + vb0.x * sc1 + vc0.x * sc2 + vd0.x * sc3;
        acc.y += va0.y * sc0 + vb0.y * sc1 + vc0.y * sc2 + vd0.y * sc3;
        acc.z += va1.x * sc0 + vb1.x * sc1 + vc1.x * sc2 + vd1.x * sc3;
        acc.w += va1.y * sc0 + vb1.y * sc1 + vc1.y * sc2 + vd1.y * sc3;
        accZ  += sc0 + sc1 + sc2 + sc3;
    }
    for (; j < end; j++) {
        int s0 = g_es[j];
        uint4 kv0 = *(const uint4*)&g_KV[s0 * 256 + slot];
        float2 k0, k1, v0, v1; kv_unpack(kv0, k0, k1, v0, v1);
        float sc0 = edge_score4(k0, k1, q4);
        acc.x += v0.x * sc0; acc.y += v0.y * sc0;
        acc.z += v1.x * sc0; acc.w += v1.y * sc0;
        accZ  += sc0;
    }

    *(float4*)&out[node * HD + lane * 4] =
        make_float4(acc.x / accZ, acc.y / accZ, acc.z / accZ, acc.w / accZ);
}

// ------------------------------------------------------------------------
extern "C" void kernel_launch(void* const* d_in, const int* in_sizes, int n_in,
                              void* d_out, int out_size) {
    const float* state = (const float*)d_in[0];
    const int*   src   = (const int*)d_in[1];
    const int*   dst   = (const int*)d_in[2];
    const float* WQ    = (const float*)d_in[3];
    const float* bQ    = (const float*)d_in[4];
    const float* WK    = (const float*)d_in[5];
    const float* bK    = (const float*)d_in[6];
    const float* WV    = (const float*)d_in[7];
    const float* bV    = (const float*)d_in[8];
    float* out = (float*)d_out;

    // Side stream + events for CSR-build || proj-GEMM overlap.
    static cudaStream_t s_csr = nullptr;
    static cudaEvent_t  ev_fork = nullptr, ev_join = nullptr;
    if (s_csr == nullptr) {
        cudaStreamCreateWithFlags(&s_csr, cudaStreamNonBlocking);
        cudaEventCreateWithFlags(&ev_fork, cudaEventDisableTiming);
        cudaEventCreateWithFlags(&ev_join, cudaEventDisableTiming);
    }

    // Fork: CSR build on side stream
    cudaEventRecord(ev_fork, 0);
    cudaStreamWaitEvent(s_csr, ev_fork, 0);

    zero_cnt_kernel<<<(N_NODES + 255) / 256, 256, 0, s_csr>>>();
    {
        int nthr = (N_EDGES + 3) / 4;
        hist_kernel<<<(nthr + 255) / 256, 256, 0, s_csr>>>(dst);
    }
    scan_kernel<<<1, 1024, 0, s_csr>>>();
    {
        int nthr = (N_EDGES + 3) / 4;
        scatter_kernel<<<(nthr + 255) / 256, 256, 0, s_csr>>>(src, dst);
    }
    cudaEventRecord(ev_join, s_csr);

    // Meanwhile: Q/K/V projections (f32x2-packed GEMM) on main stream
    const size_t smem_bytes = (size_t)(128 * 129 + 128 * 128) * sizeof(float);
    cudaFuncSetAttribute(proj_kernel, cudaFuncAttributeMaxDynamicSharedMemorySize,
                         (int)smem_bytes);
    dim3 pg((N_NODES + 127) / 128, 3);
    proj_kernel<<<pg, 256, smem_bytes>>>(state, WQ, bQ, WK, bK, WV, bV);

    // Join: agg needs both CSR and projections
    cudaStreamWaitEvent(0, ev_join, 0);

    long long nthreads = (long long)N_NODES * 32;
    int nblocks = (int)((nthreads + 255) / 256);
    agg_kernel<<<nblocks, 256>>>(out);
}